// round 1
// baseline (speedup 1.0000x reference)
#include <cuda_runtime.h>
#include <cstdint>

#define TOKENS   16384
#define DIM      4096
#define NEXP     64
#define TOPK     8
#define BT       64            // tokens per block
#define KC       32            // k-chunk
#define NC       (DIM / KC)    // 128 chunks
#define SROW     66            // padded smem row (even -> 8B-aligned LDS.64; dodges STS conflicts)
#define NTHREADS 128

#define NEG_INF (-3.0e38f)

__global__ __launch_bounds__(NTHREADS, 2)
void router_kernel(const float* __restrict__ x,
                   const float* __restrict__ W,
                   float* __restrict__ out,
                   int out_size)
{
    // two stage buffers; each stage: xs[KC][SROW] then ws[KC][SROW]
    __shared__ float smem[2 * 2 * KC * SROW];

    const int tid  = threadIdx.x;
    const int tok0 = blockIdx.x * BT;

    const int eg = tid & 15;   // expert group: experts eg*4 .. eg*4+3
    const int tg = tid >> 4;   // token group : tokens  tg*8 .. tg*8+7

    // accumulators: 4 token-pairs x 4 experts, packed f32x2 over (t, t+1)
    unsigned long long acc[4][4];
#pragma unroll
    for (int i = 0; i < 4; i++)
#pragma unroll
        for (int j = 0; j < 4; j++) acc[i][j] = 0ull;

    // loader mapping: idx = r*128 + tid -> row = idx>>3 (0..63), q = idx&7 (kk quad)
    float4 xv[4], wv[4];

    // ---- prefetch chunk 0 ----
#pragma unroll
    for (int r = 0; r < 4; r++) {
        int idx = r * NTHREADS + tid;
        int row = idx >> 3, q = idx & 7;
        xv[r] = *(const float4*)&x[(size_t)(tok0 + row) * DIM + q * 4];
        wv[r] = *(const float4*)&W[(size_t)row * DIM + q * 4];
    }

    for (int c = 0; c < NC; c++) {
        float* buf = smem + (c & 1) * (2 * KC * SROW);
        float* bx  = buf;
        float* bw  = buf + KC * SROW;

        __syncthreads();   // buffer (c&1) free: its last readers finished at iter c-2

        // store prefetched chunk c (transposed: [kk][row])
#pragma unroll
        for (int r = 0; r < 4; r++) {
            int idx = r * NTHREADS + tid;
            int row = idx >> 3, q = idx & 7;
            float* xd = bx + (q * 4) * SROW + row;
            xd[0 * SROW] = xv[r].x; xd[1 * SROW] = xv[r].y;
            xd[2 * SROW] = xv[r].z; xd[3 * SROW] = xv[r].w;
            float* wd = bw + (q * 4) * SROW + row;
            wd[0 * SROW] = wv[r].x; wd[1 * SROW] = wv[r].y;
            wd[2 * SROW] = wv[r].z; wd[3 * SROW] = wv[r].w;
        }

        // issue gmem loads for chunk c+1 (latency hidden under compute below)
        if (c + 1 < NC) {
            int koff = (c + 1) * KC;
#pragma unroll
            for (int r = 0; r < 4; r++) {
                int idx = r * NTHREADS + tid;
                int row = idx >> 3, q = idx & 7;
                xv[r] = *(const float4*)&x[(size_t)(tok0 + row) * DIM + koff + q * 4];
                wv[r] = *(const float4*)&W[(size_t)row * DIM + koff + q * 4];
            }
        }

        __syncthreads();

        // ---- compute over chunk c ----
#pragma unroll 8
        for (int kk = 0; kk < KC; kk++) {
            const float* xr = bx + kk * SROW + tg * 8;
            unsigned long long xp[4];
#pragma unroll
            for (int i = 0; i < 4; i++) {
                float2 v = *(const float2*)(xr + 2 * i);     // 8B-aligned (SROW even, offset even)
                asm("mov.b64 %0, {%1, %2};" : "=l"(xp[i]) : "f"(v.x), "f"(v.y));
            }
            const float* wr = bw + kk * SROW + eg * 4;
#pragma unroll
            for (int j = 0; j < 4; j++) {
                float w = wr[j];
                unsigned long long wd;
                asm("mov.b64 %0, {%1, %1};" : "=l"(wd) : "f"(w));
#pragma unroll
                for (int i = 0; i < 4; i++)
                    asm("fma.rn.f32x2 %0, %1, %2, %0;"
                        : "+l"(acc[i][j]) : "l"(xp[i]), "l"(wd));
            }
        }
    }

    // ---- dump logits to smem: lg[64][SROW] ----
    __syncthreads();
    float* lg = smem;
#pragma unroll
    for (int i = 0; i < 4; i++) {
#pragma unroll
        for (int j = 0; j < 4; j++) {
            float lo, hi;
            asm("mov.b64 {%0, %1}, %2;" : "=f"(lo), "=f"(hi) : "l"(acc[i][j]));
            int e = eg * 4 + j;
            lg[(tg * 8 + 2 * i)     * SROW + e] = lo;
            lg[(tg * 8 + 2 * i + 1) * SROW + e] = hi;
        }
    }
    __syncthreads();

    // ---- fused top-8 + softmax: one thread per token ----
    if (tid < BT) {
        const int t = tid;
        float* row = lg + t * SROW;

        float cv[TOPK];
        int   ci[TOPK];
#pragma unroll
        for (int r = 0; r < TOPK; r++) {
            float best = NEG_INF;
            int   bi   = 0;
            for (int e = 0; e < NEXP; e++) {
                float v = row[e];
                if (v > best) { best = v; bi = e; }   // strict > : ties pick lowest index (matches lax.top_k)
            }
            row[bi] = NEG_INF;
            cv[r] = best;
            ci[r] = bi;
        }

        // softmax over the 8 selected values (cv[0] is the max)
        float m = cv[0];
        float ex[TOPK], s = 0.f;
#pragma unroll
        for (int r = 0; r < TOPK; r++) { ex[r] = __expf(cv[r] - m); s += ex[r]; }
        float inv = 1.f / s;

        int gt = tok0 + t;
#pragma unroll
        for (int r = 0; r < TOPK; r++)
            out[gt * TOPK + r] = ex[r] * inv;

        // indices as numeric floats in the second half (if the buffer has room for them)
        if (out_size >= 2 * TOKENS * TOPK) {
#pragma unroll
            for (int r = 0; r < TOPK; r++)
                out[TOKENS * TOPK + gt * TOPK + r] = (float)ci[r];
        }
    }
}

extern "C" void kernel_launch(void* const* d_in, const int* in_sizes, int n_in,
                              void* d_out, int out_size)
{
    const float* x = (const float*)d_in[0];   // [16384, 4096]
    const float* W = (const float*)d_in[1];   // [64, 4096]
    float* out = (float*)d_out;

    router_kernel<<<TOKENS / BT, NTHREADS>>>(x, W, out, out_size);
}